// round 4
// baseline (speedup 1.0000x reference)
#include <cuda_runtime.h>
#include <cub/cub.cuh>

// Problem constants (fixed by the reference setup_inputs)
constexpr int B  = 64;
constexpr int H  = 512;
constexpr int W  = 512;
constexpr int HW = H * W;        // 262144 = 2^18
constexpr int N  = B * HW;       // 16777216 = 4096 * 4096

constexpr int THREADS = 256;
constexpr int TILE    = 4096;
constexpr int ITEMS   = TILE / THREADS;  // 16
constexpr int NB      = N / TILE;        // 4096 blocks

// Static scratch (no allocation allowed)
__device__ unsigned g_keys_a[N];
__device__ unsigned g_keys_b[N];
__device__ unsigned g_vals_a[N];
__device__ unsigned g_vals_b[N];
__device__ unsigned g_bhist[64 * NB];
__device__ unsigned g_boff[64 * NB];
__device__ unsigned char g_temp[64 << 20];

// ---------------------------------------------------------------------------
// Kernel 1: 8-neighbor NMS (comparisons on ORIGINAL values) + key encode.
//   keys[g] = descending-ordered bit mapping of suppressed score
//   vals[g] = g (global index). Stable ascending radix sort == argsort(-score).
// ---------------------------------------------------------------------------
__global__ void nms_encode_kernel(const float* __restrict__ hm,
                                  unsigned* __restrict__ keys,
                                  unsigned* __restrict__ vals) {
    int g = blockIdx.x * blockDim.x + threadIdx.x;
    if (g >= N) return;
    int idx = g & (HW - 1);
    int b   = g >> 18;
    int y   = idx >> 9;
    int x   = idx & (W - 1);

    const float* img = hm + (size_t)b * HW;
    float v = __ldg(img + idx);

    float m = -__int_as_float(0x7f800000);  // -inf
    if (y > 0) {
        const float* r = img + (y - 1) * W + x;
        if (x > 0)      m = fmaxf(m, __ldg(r - 1));
        m = fmaxf(m, __ldg(r));
        if (x < W - 1)  m = fmaxf(m, __ldg(r + 1));
    }
    {
        const float* r = img + y * W + x;
        if (x > 0)      m = fmaxf(m, __ldg(r - 1));
        if (x < W - 1)  m = fmaxf(m, __ldg(r + 1));
    }
    if (y < H - 1) {
        const float* r = img + (y + 1) * W + x;
        if (x > 0)      m = fmaxf(m, __ldg(r - 1));
        m = fmaxf(m, __ldg(r));
        if (x < W - 1)  m = fmaxf(m, __ldg(r + 1));
    }

    float jv = (m >= v) ? 0.6f * v : v;

    unsigned u = __float_as_uint(jv);
    unsigned e = u ^ (((unsigned)((int)u >> 31)) | 0x80000000u);
    keys[g] = ~e;
    vals[g] = (unsigned)g;
}

// ---------------------------------------------------------------------------
// Kernel 2: per-block 64-bin batch histogram over the score-sorted values.
// ---------------------------------------------------------------------------
__global__ void hist_kernel(const unsigned* __restrict__ vs,
                            unsigned* __restrict__ bh) {
    __shared__ unsigned cnt[64];
    int t = threadIdx.x;
    if (t < 64) cnt[t] = 0;
    __syncthreads();
    const uint4* v4 = (const uint4*)(vs + (size_t)blockIdx.x * TILE);
    for (int i = t; i < TILE / 4; i += THREADS) {
        uint4 q = v4[i];
        atomicAdd(&cnt[q.x >> 18], 1u);
        atomicAdd(&cnt[q.y >> 18], 1u);
        atomicAdd(&cnt[q.z >> 18], 1u);
        atomicAdd(&cnt[q.w >> 18], 1u);
    }
    __syncthreads();
    if (t < 64) bh[(size_t)t * NB + blockIdx.x] = cnt[t];
}

// ---------------------------------------------------------------------------
// Kernel 3: exclusive scan of per-block counts for one batch per block,
// plus the batch base offset b*HW.
// ---------------------------------------------------------------------------
__global__ void scan_kernel(const unsigned* __restrict__ bh,
                            unsigned* __restrict__ bo) {
    typedef cub::BlockScan<unsigned, 1024> BS;
    __shared__ typename BS::TempStorage ts;
    int b = blockIdx.x;
    const unsigned* src = bh + (size_t)b * NB;
    unsigned* dst = bo + (size_t)b * NB;
    unsigned v[4];
#pragma unroll
    for (int i = 0; i < 4; i++) v[i] = src[threadIdx.x * 4 + i];
    BS(ts).ExclusiveSum(v, v);
    unsigned base = (unsigned)b * (unsigned)HW;
#pragma unroll
    for (int i = 0; i < 4; i++) dst[threadIdx.x * 4 + i] = v[i] + base;
}

// ---------------------------------------------------------------------------
// Kernel 4: fused stable 64-way partition scatter + decode.
// BLOCKED load (thread t owns 16 consecutive elements) so register order ==
// memory order; cub::BlockRadixRank provides the stable in-tile rank.
// ---------------------------------------------------------------------------
typedef cub::BlockRadixRank<THREADS, 6, false> BRR;

struct BatchExtractor {
    __device__ __forceinline__ unsigned Digit(unsigned key) const {
        return key >> 18;
    }
};

__global__ void scatter_decode_kernel(const unsigned* __restrict__ vs,
                                      const unsigned* __restrict__ ds,
                                      const unsigned* __restrict__ bo,
                                      const float* __restrict__ off,
                                      float* __restrict__ out) {
    __shared__ typename BRR::TempStorage rank_storage;
    __shared__ unsigned sh_base[64];

    int t = threadIdx.x;
    size_t base = (size_t)blockIdx.x * TILE + (size_t)t * ITEMS;

    unsigned v[ITEMS], d[ITEMS];
    const uint4* v4 = (const uint4*)(vs + base);
    const uint4* d4 = (const uint4*)(ds + base);
#pragma unroll
    for (int j = 0; j < ITEMS / 4; j++) {
        uint4 q = v4[j];
        v[4 * j + 0] = q.x; v[4 * j + 1] = q.y;
        v[4 * j + 2] = q.z; v[4 * j + 3] = q.w;
        uint4 p = d4[j];
        d[4 * j + 0] = p.x; d[4 * j + 1] = p.y;
        d[4 * j + 2] = p.z; d[4 * j + 3] = p.w;
    }

    int ranks[ITEMS];
    int exc[BRR::BINS_TRACKED_PER_THREAD];
    BatchExtractor ext;
    BRR(rank_storage).RankKeys(v, ranks, ext, exc);

    // Thread t (< 64) tracks digit t: combine global tile offset for batch t
    // with the tile-exclusive prefix of batch t.
    if (t < 64)
        sh_base[t] = bo[(size_t)t * NB + blockIdx.x] - (unsigned)exc[0];
    __syncthreads();

#pragma unroll
    for (int i = 0; i < ITEMS; i++) {
        unsigned b   = v[i] >> 18;
        unsigned idx = v[i] & 0x3FFFFu;
        unsigned pos = sh_base[b] + (unsigned)ranks[i];

        unsigned e = ~d[i];
        unsigned msk = (e & 0x80000000u) ? 0x80000000u : 0xFFFFFFFFu;
        float score = __uint_as_float(e ^ msk);
        int y = idx >> 9, x = idx & (W - 1);

        const float* ob = off + (size_t)b * 2 * HW;
        float xo = __ldg(ob + idx);        // channel 0: x-offset
        float yo = __ldg(ob + HW + idx);   // channel 1: y-offset

        float* o = out + (size_t)pos * 3;
        o[0] = (float)y + yo + 0.5f;
        o[1] = (float)x + xo + 0.5f;
        o[2] = score;
    }
}

extern "C" void kernel_launch(void* const* d_in, const int* in_sizes, int n_in,
                              void* d_out, int out_size) {
    const float* hm  = (const float*)d_in[0];
    const float* off = (const float*)d_in[1];
    float* out = (float*)d_out;

    unsigned *ka = nullptr, *kb = nullptr, *va = nullptr, *vb = nullptr;
    unsigned *bh = nullptr, *bo = nullptr;
    void* tmp = nullptr;
    cudaGetSymbolAddress((void**)&ka, g_keys_a);
    cudaGetSymbolAddress((void**)&kb, g_keys_b);
    cudaGetSymbolAddress((void**)&va, g_vals_a);
    cudaGetSymbolAddress((void**)&vb, g_vals_b);
    cudaGetSymbolAddress((void**)&bh, g_bhist);
    cudaGetSymbolAddress((void**)&bo, g_boff);
    cudaGetSymbolAddress(&tmp, g_temp);

    const int blocks = (N + THREADS - 1) / THREADS;
    nms_encode_kernel<<<blocks, THREADS>>>(hm, ka, va);

    // Stable sort by 32-bit descending-mapped score (4 onesweep passes).
    cub::DoubleBuffer<unsigned> dkeys(ka, kb);
    cub::DoubleBuffer<unsigned> dvals(va, vb);
    size_t temp_bytes = sizeof(g_temp);
    cub::DeviceRadixSort::SortPairs(tmp, temp_bytes, dkeys, dvals, N,
                                    0, 32, /*stream=*/0);

    const unsigned* vs = dvals.Current();
    const unsigned* ds = dkeys.Current();

    hist_kernel<<<NB, THREADS>>>(vs, bh);
    scan_kernel<<<64, 1024>>>(bh, bo);
    scatter_decode_kernel<<<NB, THREADS>>>(vs, ds, bo, off, out);
}

// round 5
// speedup vs baseline: 1.2798x; 1.2798x over previous
#include <cuda_runtime.h>
#include <cub/cub.cuh>

// Problem constants (fixed by the reference setup_inputs)
constexpr int B  = 64;
constexpr int H  = 512;
constexpr int W  = 512;
constexpr int HW = H * W;        // 262144 = 2^18
constexpr int N  = B * HW;       // 16777216 = 4096 * 4096

constexpr int THREADS = 256;
constexpr int TILE    = 4096;
constexpr int ITEMS   = TILE / THREADS;  // 16
constexpr int NB      = N / TILE;        // 4096 blocks

// Static scratch (no allocation allowed)
__device__ unsigned g_keys_a[N];
__device__ unsigned g_keys_b[N];
__device__ unsigned g_vals_a[N];
__device__ unsigned g_vals_b[N];
__device__ float2   g_pairs[N];          // interleaved (xo, yo) per (b, idx)
__device__ unsigned g_bhist[64 * NB];
__device__ unsigned g_boff[64 * NB];
__device__ unsigned char g_temp[64 << 20];

// ---------------------------------------------------------------------------
// Kernel 1: 8-neighbor NMS + key encode + offset-pair interleave.
//   keys[g] = descending-ordered bit mapping of suppressed score
//   vals[g] = g (global index)
//   pairs[g] = {x-offset, y-offset}   (one 8B gather later instead of two 4B)
// ---------------------------------------------------------------------------
__global__ void nms_encode_kernel(const float* __restrict__ hm,
                                  const float* __restrict__ off,
                                  unsigned* __restrict__ keys,
                                  unsigned* __restrict__ vals,
                                  float2* __restrict__ pairs) {
    int g = blockIdx.x * blockDim.x + threadIdx.x;
    if (g >= N) return;
    int idx = g & (HW - 1);
    int b   = g >> 18;
    int y   = idx >> 9;
    int x   = idx & (W - 1);

    const float* img = hm + (size_t)b * HW;
    float v = __ldg(img + idx);

    float m = -__int_as_float(0x7f800000);  // -inf
    if (y > 0) {
        const float* r = img + (y - 1) * W + x;
        if (x > 0)      m = fmaxf(m, __ldg(r - 1));
        m = fmaxf(m, __ldg(r));
        if (x < W - 1)  m = fmaxf(m, __ldg(r + 1));
    }
    {
        const float* r = img + y * W + x;
        if (x > 0)      m = fmaxf(m, __ldg(r - 1));
        if (x < W - 1)  m = fmaxf(m, __ldg(r + 1));
    }
    if (y < H - 1) {
        const float* r = img + (y + 1) * W + x;
        if (x > 0)      m = fmaxf(m, __ldg(r - 1));
        m = fmaxf(m, __ldg(r));
        if (x < W - 1)  m = fmaxf(m, __ldg(r + 1));
    }

    float jv = (m >= v) ? 0.6f * v : v;

    unsigned u = __float_as_uint(jv);
    unsigned e = u ^ (((unsigned)((int)u >> 31)) | 0x80000000u);
    keys[g] = ~e;
    vals[g] = (unsigned)g;

    const float* ob = off + (size_t)b * 2 * HW;
    float xo = __ldg(ob + idx);        // channel 0: x-offset
    float yo = __ldg(ob + HW + idx);   // channel 1: y-offset
    pairs[g] = make_float2(xo, yo);
}

// ---------------------------------------------------------------------------
// Kernel 2: per-block 64-bin batch histogram over the score-sorted values.
// ---------------------------------------------------------------------------
__global__ void hist_kernel(const unsigned* __restrict__ vs,
                            unsigned* __restrict__ bh) {
    __shared__ unsigned cnt[64];
    int t = threadIdx.x;
    if (t < 64) cnt[t] = 0;
    __syncthreads();
    const uint4* v4 = (const uint4*)(vs + (size_t)blockIdx.x * TILE);
    for (int i = t; i < TILE / 4; i += THREADS) {
        uint4 q = v4[i];
        atomicAdd(&cnt[q.x >> 18], 1u);
        atomicAdd(&cnt[q.y >> 18], 1u);
        atomicAdd(&cnt[q.z >> 18], 1u);
        atomicAdd(&cnt[q.w >> 18], 1u);
    }
    __syncthreads();
    if (t < 64) bh[(size_t)t * NB + blockIdx.x] = cnt[t];
}

// ---------------------------------------------------------------------------
// Kernel 3: exclusive scan of per-block counts for one batch per block,
// plus the batch base offset b*HW.
// ---------------------------------------------------------------------------
__global__ void scan_kernel(const unsigned* __restrict__ bh,
                            unsigned* __restrict__ bo) {
    typedef cub::BlockScan<unsigned, 1024> BS;
    __shared__ typename BS::TempStorage ts;
    int b = blockIdx.x;
    const unsigned* src = bh + (size_t)b * NB;
    unsigned* dst = bo + (size_t)b * NB;
    unsigned v[4];
#pragma unroll
    for (int i = 0; i < 4; i++) v[i] = src[threadIdx.x * 4 + i];
    BS(ts).ExclusiveSum(v, v);
    unsigned base = (unsigned)b * (unsigned)HW;
#pragma unroll
    for (int i = 0; i < 4; i++) dst[threadIdx.x * 4 + i] = v[i] + base;
}

// ---------------------------------------------------------------------------
// Kernel 4: fused stable 64-way partition + decode with SMEM staging.
// BLOCKED load (register order == memory order) -> stable BlockRadixRank ->
// exchange (v,d) through smem by rank -> slot-ordered processing so that
// consecutive threads write consecutive output rows (coalesced).
// ---------------------------------------------------------------------------
typedef cub::BlockRadixRank<THREADS, 6, false> BRR;

struct BatchExtractor {
    __device__ __forceinline__ unsigned Digit(unsigned key) const {
        return key >> 18;
    }
};

__global__ void scatter_decode_kernel(const unsigned* __restrict__ vs,
                                      const unsigned* __restrict__ ds,
                                      const unsigned* __restrict__ bo,
                                      const float2* __restrict__ pairs,
                                      float* __restrict__ out) {
    __shared__ union SM {
        typename BRR::TempStorage rank;
        struct { unsigned v[TILE]; unsigned d[TILE]; } ex;
        __device__ SM() {}
    } sm;
    __shared__ unsigned sh_base[64];

    int t = threadIdx.x;
    size_t base = (size_t)blockIdx.x * TILE + (size_t)t * ITEMS;

    unsigned v[ITEMS], d[ITEMS];
    const uint4* v4 = (const uint4*)(vs + base);
    const uint4* d4 = (const uint4*)(ds + base);
#pragma unroll
    for (int j = 0; j < ITEMS / 4; j++) {
        uint4 q = v4[j];
        v[4 * j + 0] = q.x; v[4 * j + 1] = q.y;
        v[4 * j + 2] = q.z; v[4 * j + 3] = q.w;
        uint4 p = d4[j];
        d[4 * j + 0] = p.x; d[4 * j + 1] = p.y;
        d[4 * j + 2] = p.z; d[4 * j + 3] = p.w;
    }

    int ranks[ITEMS];
    int exc[BRR::BINS_TRACKED_PER_THREAD];
    BatchExtractor ext;
    BRR(sm.rank).RankKeys(v, ranks, ext, exc);

    // pos for tile slot s of batch b:  bo[b][tile] + (s - tile_prefix[b])
    if (t < 64)
        sh_base[t] = bo[(size_t)t * NB + blockIdx.x] - (unsigned)exc[0];
    __syncthreads();  // all threads done with rank storage before aliasing

    // Exchange into rank order (slot s == in-tile stable rank)
#pragma unroll
    for (int i = 0; i < ITEMS; i++) sm.ex.v[ranks[i]] = v[i];
#pragma unroll
    for (int i = 0; i < ITEMS; i++) sm.ex.d[ranks[i]] = d[i];
    __syncthreads();

#pragma unroll
    for (int k = 0; k < ITEMS; k++) {
        int s = t + k * THREADS;
        unsigned vv = sm.ex.v[s];
        unsigned dd = sm.ex.d[s];
        unsigned b   = vv >> 18;
        unsigned idx = vv & 0x3FFFFu;
        unsigned pos = sh_base[b] + (unsigned)s;

        unsigned e = ~dd;
        unsigned msk = (e & 0x80000000u) ? 0x80000000u : 0xFFFFFFFFu;
        float score = __uint_as_float(e ^ msk);
        int y = idx >> 9, x = idx & (W - 1);

        float2 p = __ldg(&pairs[((size_t)b << 18) | idx]);

        float* o = out + (size_t)pos * 3;
        o[0] = (float)y + p.y + 0.5f;   // p.y = y-offset
        o[1] = (float)x + p.x + 0.5f;   // p.x = x-offset
        o[2] = score;
    }
}

extern "C" void kernel_launch(void* const* d_in, const int* in_sizes, int n_in,
                              void* d_out, int out_size) {
    const float* hm  = (const float*)d_in[0];
    const float* off = (const float*)d_in[1];
    float* out = (float*)d_out;

    unsigned *ka = nullptr, *kb = nullptr, *va = nullptr, *vb = nullptr;
    unsigned *bh = nullptr, *bo = nullptr;
    float2* pr = nullptr;
    void* tmp = nullptr;
    cudaGetSymbolAddress((void**)&ka, g_keys_a);
    cudaGetSymbolAddress((void**)&kb, g_keys_b);
    cudaGetSymbolAddress((void**)&va, g_vals_a);
    cudaGetSymbolAddress((void**)&vb, g_vals_b);
    cudaGetSymbolAddress((void**)&bh, g_bhist);
    cudaGetSymbolAddress((void**)&bo, g_boff);
    cudaGetSymbolAddress((void**)&pr, g_pairs);
    cudaGetSymbolAddress(&tmp, g_temp);

    const int blocks = (N + THREADS - 1) / THREADS;
    nms_encode_kernel<<<blocks, THREADS>>>(hm, off, ka, va, pr);

    // Stable sort by 32-bit descending-mapped score (4 onesweep passes).
    cub::DoubleBuffer<unsigned> dkeys(ka, kb);
    cub::DoubleBuffer<unsigned> dvals(va, vb);
    size_t temp_bytes = sizeof(g_temp);
    cub::DeviceRadixSort::SortPairs(tmp, temp_bytes, dkeys, dvals, N,
                                    0, 32, /*stream=*/0);

    const unsigned* vs = dvals.Current();
    const unsigned* ds = dkeys.Current();

    hist_kernel<<<NB, THREADS>>>(vs, bh);
    scan_kernel<<<64, 1024>>>(bh, bo);
    scatter_decode_kernel<<<NB, THREADS>>>(vs, ds, bo, pr, out);
}